// round 14
// baseline (speedup 1.0000x reference)
#include <cuda_runtime.h>
#include <cuda_fp16.h>
#include <mma.h>
#include <math.h>
#include <cstdint>

using namespace nvcuda;

#define BB 2
#define TT 2048
#define DD 1024
#define HH 16
#define HD 64
#define NROWS (BB*TT)      // 4096
#define WINDOW 128
#define MM (1024*1024)

// ---------------- scratch (device globals: allocation-free) ----------------
__device__ __half g_q[(size_t)BB*HH*TT*HD];   // normalized q (fp16)
__device__ __half g_k[(size_t)BB*HH*TT*HD];   // normalized k (fp16)
__device__ __half g_v[(size_t)BB*HH*TT*HD];   // v (fp16)
__device__ __half g_xh[(size_t)NROWS*DD];     // x (fp16)
__device__ __half g_wh[(size_t)4*MM];         // 32*W (fp16)
__device__ __half g_ath[(size_t)NROWS*DD];    // attention out (fp16)

__device__ __forceinline__ uint32_t smem_u32(const void* p){
    uint32_t a;
    asm("{ .reg .u64 t; cvta.to.shared.u64 t, %1; cvt.u32.u64 %0, t; }" : "=r"(a) : "l"(p));
    return a;
}
__device__ __forceinline__ void cp16(uint32_t s, const void* g){
    asm volatile("cp.async.cg.shared.global [%0], [%1], 16;" :: "r"(s), "l"(g));
}

// =====================================================================
// split prep: x -> fp16 ; W -> fp16(32*W)
// =====================================================================
__global__ void __launch_bounds__(256) split_kernel(
    const float* __restrict__ x,
    const float* __restrict__ wq, const float* __restrict__ wk,
    const float* __restrict__ wv, const float* __restrict__ wo)
{
    size_t fi = (size_t)blockIdx.x*256 + threadIdx.x;
    if (fi < 1048576){
        float4 v = ((const float4*)x)[fi];
        size_t e = fi*4;
        *(half2*)(g_xh+e)   = half2(__float2half(v.x), __float2half(v.y));
        *(half2*)(g_xh+e+2) = half2(__float2half(v.z), __float2half(v.w));
    } else {
        size_t r = fi - 1048576;
        int m = (int)(r >> 18);
        size_t base = r & 262143;
        const float* src = (m==0)?wq:(m==1)?wk:(m==2)?wv:wo;
        float4 v = ((const float4*)src)[base];
        size_t e = (size_t)m*MM + base*4;
        *(half2*)(g_wh+e)   = half2(__float2half(32.0f*v.x), __float2half(32.0f*v.y));
        *(half2*)(g_wh+e+2) = half2(__float2half(32.0f*v.z), __float2half(32.0f*v.w));
    }
}

// ---------------- shared GEMM geometry ----------------
#define NCH 16
#define SSTRIDE 72
#define SARR 9216                        // 128 rows x 72 el
#define STAGE_EL (2*SARR)                // 18432 el
#define STAGE_BY (STAGE_EL*2)            // 36864 B
#define GEMM_SMEM 73728

// =====================================================================
// q/k GEMM: fp16 ACCUMULATORS (2x-rate experiment). cols [0,2048).
// CTA 128x128, warp 64x32, BK=64, 2 CTAs/SM. l2norm epilogue always.
// =====================================================================
__global__ void __launch_bounds__(256, 2) gemm_qk_kernel()
{
    extern __shared__ __half sb[];
    __half* Csh = sb;                             // [128][136] half after mainloop

    const int tid = threadIdx.x, w = tid >> 5, lane = tid & 31;
    const int r0 = blockIdx.y * 128;
    const int nb = blockIdx.x * 128;              // 0..1920
    const int which = nb >> 10;                   // 0 (q) or 1 (k)
    const int col0 = nb & 1023;
    const __half* A_h = g_xh;
    const __half* W_h = g_wh + (size_t)which*MM;

    const uint32_t ab = smem_u32(sb);

    auto loadc = [&](int c){
        uint32_t st = ab + (uint32_t)(c & 1) * STAGE_BY;
        int ko = c * 64;
        #pragma unroll
        for (int i = 0; i < 4; i++){
            int idx = tid + i*256;
            int row = idx >> 3, seg = idx & 7;
            uint32_t so = (uint32_t)(row*144 + seg*16);
            cp16(st + so,          A_h + (size_t)(r0  + row)*DD + ko + seg*8);
            cp16(st + 18432u + so, W_h + (size_t)(col0 + row)*DD + ko + seg*8);
        }
        asm volatile("cp.async.commit_group;");
    };

    wmma::fragment<wmma::accumulator,16,16,16,__half> acc[4][2];
    #pragma unroll
    for (int i = 0; i < 4; i++)
        #pragma unroll
        for (int j = 0; j < 2; j++) wmma::fill_fragment(acc[i][j], __float2half(0.0f));

    const int wm = (w >> 2) * 64;
    const int wn = (w & 3) * 32;

    loadc(0);
    for (int c = 0; c < NCH; c++){
        if (c < NCH-1){
            loadc(c+1);
            asm volatile("cp.async.wait_group 1;");
        } else {
            asm volatile("cp.async.wait_group 0;");
        }
        __syncthreads();

        const __half* s = sb + (c & 1) * STAGE_EL;
        const __half* sA = s;
        const __half* sB = s + SARR;

        #pragma unroll
        for (int kk = 0; kk < 64; kk += 16){
            wmma::fragment<wmma::matrix_a,16,16,16,__half,wmma::row_major> af[4];
            wmma::fragment<wmma::matrix_b,16,16,16,__half,wmma::col_major> bf[2];
            #pragma unroll
            for (int i = 0; i < 4; i++)
                wmma::load_matrix_sync(af[i], sA + (wm + i*16)*SSTRIDE + kk, SSTRIDE);
            #pragma unroll
            for (int j = 0; j < 2; j++)
                wmma::load_matrix_sync(bf[j], sB + (wn + j*16)*SSTRIDE + kk, SSTRIDE);
            #pragma unroll
            for (int i = 0; i < 4; i++)
                #pragma unroll
                for (int j = 0; j < 2; j++)
                    wmma::mma_sync(acc[i][j], af[i], bf[j], acc[i][j]);
        }
        __syncthreads();
    }

    // stage C (half) in smem [128][136]
    #pragma unroll
    for (int i = 0; i < 4; i++)
        #pragma unroll
        for (int j = 0; j < 2; j++)
            wmma::store_matrix_sync(Csh + (wm + i*16)*136 + wn + j*16,
                                    acc[i][j], 136, wmma::mem_row_major);
    __syncthreads();

    // epilogue: l2norm per head (scale cancels the x32 weight scaling)
    #pragma unroll
    for (int rr = 0; rr < 16; rr++){
        int row = w*16 + rr;
        int gt = r0 + row;
        float v0 = __half2float(Csh[row*136 + lane]);
        float v1 = __half2float(Csh[row*136 + lane + 32]);
        float v2 = __half2float(Csh[row*136 + lane + 64]);
        float v3 = __half2float(Csh[row*136 + lane + 96]);
        float ssa = v0*v0 + v1*v1;
        float ssb = v2*v2 + v3*v3;
        #pragma unroll
        for (int o = 16; o; o >>= 1){
            ssa += __shfl_xor_sync(0xffffffffu, ssa, o);
            ssb += __shfl_xor_sync(0xffffffffu, ssb, o);
        }
        float s0 = 1.0f / fmaxf(sqrtf(ssa), 1e-6f);
        float s1 = 1.0f / fmaxf(sqrtf(ssb), 1e-6f);
        int bq = gt >> 11, t = gt & (TT-1);
        __half* arr = (which==0) ? g_q : g_k;
        int hh0 = col0 >> 6;
        __half* d0 = arr + ((size_t)(bq*HH + hh0  )*TT + t)*HD;
        __half* d1 = arr + ((size_t)(bq*HH + hh0+1)*TT + t)*HD;
        d0[lane]      = __float2half(v0*s0);
        d0[lane + 32] = __float2half(v1*s0);
        d1[lane]      = __float2half(v2*s1);
        d1[lane + 32] = __float2half(v3*s1);
    }
}

// =====================================================================
// GEMM (fp32 acc): mode 0 = v (nbase=2048), mode 1 = Wo.
// =====================================================================
__global__ void __launch_bounds__(256, 2) gemm_kernel(float* __restrict__ out,
                                                      int mode, int nbase)
{
    extern __shared__ __half sb[];
    float* Cs = (float*)sb;                       // [128][132] after mainloop

    const int tid = threadIdx.x, w = tid >> 5, lane = tid & 31;
    const int r0 = blockIdx.y * 128;
    const int nb = nbase + blockIdx.x * 128;

    int which, col0;
    const __half* A_h;
    if (mode == 0){ which = nb >> 10; col0 = nb & 1023; A_h = g_xh; }
    else          { which = 3;        col0 = nb;        A_h = g_ath; }
    const __half* W_h = g_wh + (size_t)which*MM;

    const uint32_t ab = smem_u32(sb);

    auto loadc = [&](int c){
        uint32_t st = ab + (uint32_t)(c & 1) * STAGE_BY;
        int ko = c * 64;
        #pragma unroll
        for (int i = 0; i < 4; i++){
            int idx = tid + i*256;
            int row = idx >> 3, seg = idx & 7;
            uint32_t so = (uint32_t)(row*144 + seg*16);
            cp16(st + so,          A_h + (size_t)(r0  + row)*DD + ko + seg*8);
            cp16(st + 18432u + so, W_h + (size_t)(col0 + row)*DD + ko + seg*8);
        }
        asm volatile("cp.async.commit_group;");
    };

    wmma::fragment<wmma::accumulator,16,16,16,float> acc[4][2];
    #pragma unroll
    for (int i = 0; i < 4; i++)
        #pragma unroll
        for (int j = 0; j < 2; j++) wmma::fill_fragment(acc[i][j], 0.0f);

    const int wm = (w >> 2) * 64;
    const int wn = (w & 3) * 32;

    loadc(0);
    for (int c = 0; c < NCH; c++){
        if (c < NCH-1){
            loadc(c+1);
            asm volatile("cp.async.wait_group 1;");
        } else {
            asm volatile("cp.async.wait_group 0;");
        }
        __syncthreads();

        const __half* s = sb + (c & 1) * STAGE_EL;
        const __half* sA = s;
        const __half* sB = s + SARR;

        #pragma unroll
        for (int kk = 0; kk < 64; kk += 16){
            wmma::fragment<wmma::matrix_a,16,16,16,__half,wmma::row_major> af[4];
            wmma::fragment<wmma::matrix_b,16,16,16,__half,wmma::col_major> bf[2];
            #pragma unroll
            for (int i = 0; i < 4; i++)
                wmma::load_matrix_sync(af[i], sA + (wm + i*16)*SSTRIDE + kk, SSTRIDE);
            #pragma unroll
            for (int j = 0; j < 2; j++)
                wmma::load_matrix_sync(bf[j], sB + (wn + j*16)*SSTRIDE + kk, SSTRIDE);
            #pragma unroll
            for (int i = 0; i < 4; i++)
                #pragma unroll
                for (int j = 0; j < 2; j++)
                    wmma::mma_sync(acc[i][j], af[i], bf[j], acc[i][j]);
        }
        __syncthreads();
    }

    #pragma unroll
    for (int i = 0; i < 4; i++)
        #pragma unroll
        for (int j = 0; j < 2; j++)
            wmma::store_matrix_sync(Cs + (wm + i*16)*132 + wn + j*16,
                                    acc[i][j], 132, wmma::mem_row_major);
    __syncthreads();

    const float unsc = 0.03125f;   // 1/32
    #pragma unroll
    for (int rr = 0; rr < 16; rr++){
        int row = w*16 + rr;
        int gt = r0 + row;
        float v0 = Cs[row*132 + lane];
        float v1 = Cs[row*132 + lane + 32];
        float v2 = Cs[row*132 + lane + 64];
        float v3 = Cs[row*132 + lane + 96];
        if (mode == 0){
            // v block: no norm, just /32
            int bq = gt >> 11, t = gt & (TT-1);
            int hh0 = col0 >> 6;
            __half* d0 = g_v + ((size_t)(bq*HH + hh0  )*TT + t)*HD;
            __half* d1 = g_v + ((size_t)(bq*HH + hh0+1)*TT + t)*HD;
            d0[lane]      = __float2half(v0*unsc);
            d0[lane + 32] = __float2half(v1*unsc);
            d1[lane]      = __float2half(v2*unsc);
            d1[lane + 32] = __float2half(v3*unsc);
        } else {
            float* d = out + (size_t)gt*DD + nb;
            d[lane]      = v0*unsc;
            d[lane + 32] = v1*unsc;
            d[lane + 64] = v2*unsc;
            d[lane + 96] = v3*unsc;
        }
    }
}

// =====================================================================
// Attention (fp16 wmma), 512 threads, 2 BLOCKS/SM (90KB smem). unchanged.
// =====================================================================
#define ATTN_SMEM_BYTES 90112

__global__ void __launch_bounds__(512, 2) attn_kernel()
{
    extern __shared__ __half sm[];
    __half* Qs = sm;                          // [64][72]
    __half* Ks = sm + 4608;                   // [192][72] (dead after QK)
    __half* Vs = sm + 18432;                  // [192][72]
    __half* Sh = sm + 32256;                  // [64][200] half: S, then P in place
    float*  Os = (float*)(sm + 4608);         // [64][68] f32, overlays Ks

    const int tid = threadIdx.x, w = tid >> 5, lane = tid & 31;
    const int q0 = blockIdx.x * 64;
    const int h  = blockIdx.y, b = blockIdx.z;
    const size_t base = ((size_t)(b*HH + h)*TT)*HD;
    const __half* qb = g_q + base;
    const __half* kb = g_k + base;
    const __half* vb = g_v + base;

    {   // Q
        int row = tid >> 3, seg = tid & 7;
        uint4 v = *(const uint4*)(qb + (size_t)(q0 + row)*HD + seg*8);
        *(uint4*)(Qs + row*72 + seg*8) = v;
    }
    #pragma unroll
    for (int it = 0; it < 3; it++){           // K,V
        int idx = tid + it*512;
        int row = idx >> 3, seg = idx & 7;
        int jg = q0 + row;
        uint4 kv = make_uint4(0,0,0,0), vv = make_uint4(0,0,0,0);
        if (jg < TT){
            kv = *(const uint4*)(kb + (size_t)jg*HD + seg*8);
            vv = *(const uint4*)(vb + (size_t)jg*HD + seg*8);
        }
        *(uint4*)(Ks + row*72 + seg*8) = kv;
        *(uint4*)(Vs + row*72 + seg*8) = vv;
    }
    __syncthreads();

    const int wr = w & 3;
    const int wg = w >> 2;

    {   // S = Q @ K^T, fp16 accumulators
        wmma::fragment<wmma::accumulator,16,16,16,__half> acc[3];
        #pragma unroll
        for (int f = 0; f < 3; f++) wmma::fill_fragment(acc[f], __float2half(0.0f));
        #pragma unroll
        for (int d = 0; d < HD; d += 16){
            wmma::fragment<wmma::matrix_a,16,16,16,__half,wmma::row_major> af;
            wmma::load_matrix_sync(af, Qs + wr*16*72 + d, 72);
            #pragma unroll
            for (int f = 0; f < 3; f++){
                int tc = wg*3 + f;
                if (tc >= wr && tc <= wr + 8){
                    wmma::fragment<wmma::matrix_b,16,16,16,__half,wmma::col_major> bf;
                    wmma::load_matrix_sync(bf, Ks + tc*16*72 + d, 72);
                    wmma::mma_sync(acc[f], af, bf, acc[f]);
                }
            }
        }
        #pragma unroll
        for (int f = 0; f < 3; f++){
            int tc = wg*3 + f;
            if (tc >= wr && tc <= wr + 8)
                wmma::store_matrix_sync(Sh + wr*16*200 + tc*16, acc[f], 200,
                                        wmma::mem_row_major);
        }
    }
    __syncthreads();

    const float slope = exp2f(-8.0f * (float)h / 15.0f);
    #pragma unroll
    for (int rr = 0; rr < 4; rr++){
        int row = w*4 + rr;
        float vals[6];
        float m = -INFINITY;
        #pragma unroll
        for (int i = 0; i < 6; i++){
            int col = lane + 32*i;
            bool ok = (col >= row) && (col < row + WINDOW) && (q0 + col < TT);
            float s = ok ? (__half2float(Sh[row*200 + col]) - (float)(col - row)*slope)
                         : -INFINITY;
            vals[i] = s;
            m = fmaxf(m, s);
        }
        #pragma unroll
        for (int o = 16; o; o >>= 1) m = fmaxf(m, __shfl_xor_sync(0xffffffffu, m, o));
        float sum = 0.0f;
        #pragma unroll
        for (int i = 0; i < 6; i++){
            float p = (vals[i] > -INFINITY) ? __expf(vals[i] - m) : 0.0f;
            vals[i] = p; sum += p;
        }
        #pragma unroll
        for (int o = 16; o; o >>= 1) sum += __shfl_xor_sync(0xffffffffu, sum, o);
        float inv = 1.0f / sum;
        #pragma unroll
        for (int i = 0; i < 6; i++){
            int col = lane + 32*i;
            Sh[row*200 + col] = __float2half(vals[i]*inv);
        }
    }
    __syncthreads();

    {   // O = P @ V
        wmma::fragment<wmma::accumulator,16,16,16,float> acc;
        wmma::fill_fragment(acc, 0.0f);
        #pragma unroll
        for (int tj = 0; tj < 12; tj++){
            if (tj >= wr && tj <= wr + 8){
                wmma::fragment<wmma::matrix_a,16,16,16,__half,wmma::row_major> af;
                wmma::fragment<wmma::matrix_b,16,16,16,__half,wmma::row_major> bf;
                wmma::load_matrix_sync(af, Sh + wr*16*200 + tj*16, 200);
                wmma::load_matrix_sync(bf, Vs + tj*16*72 + wg*16, 72);
                wmma::mma_sync(acc, af, bf, acc);
            }
        }
        wmma::store_matrix_sync(Os + wr*16*68 + wg*16, acc, 68, wmma::mem_row_major);
    }
    __syncthreads();

    #pragma unroll
    for (int it = 0; it < 2; it++){
        int idx = tid + it*512;
        int row = idx >> 4, c4 = (idx & 15) << 2;
        float4 v = *(const float4*)(Os + row*68 + c4);
        size_t o = (size_t)(b*TT + q0 + row)*DD + h*HD + c4;
        *(half2*)(g_ath+o)   = half2(__float2half(v.x), __float2half(v.y));
        *(half2*)(g_ath+o+2) = half2(__float2half(v.z), __float2half(v.w));
    }
}

// =====================================================================
extern "C" void kernel_launch(void* const* d_in, const int* in_sizes, int n_in,
                              void* d_out, int out_size)
{
    const float* x  = (const float*)d_in[0];
    const float* Wq = (const float*)d_in[1];
    const float* Wk = (const float*)d_in[2];
    const float* Wv = (const float*)d_in[3];
    const float* Wo = (const float*)d_in[4];
    float* out = (float*)d_out;

    cudaFuncSetAttribute(gemm_qk_kernel, cudaFuncAttributeMaxDynamicSharedMemorySize,
                         GEMM_SMEM);
    cudaFuncSetAttribute(gemm_kernel, cudaFuncAttributeMaxDynamicSharedMemorySize,
                         GEMM_SMEM);
    cudaFuncSetAttribute(attn_kernel, cudaFuncAttributeMaxDynamicSharedMemorySize,
                         ATTN_SMEM_BYTES);

    // 0) fp16 conversion of x and weights (x32)
    split_kernel<<<8192, 256>>>(x, Wq, Wk, Wv, Wo);
    // 1a) q,k projections (fp16 accumulate) + l2norm  [cols 0..2047]
    gemm_qk_kernel<<<dim3(16, 32), 256, GEMM_SMEM>>>();
    // 1b) v projection (fp32 accumulate)  [cols 2048..3071]
    gemm_kernel<<<dim3(8, 32), 256, GEMM_SMEM>>>(nullptr, 0, 2048);
    // 2) sliding-window attention per (b, h, 64-query tile)
    attn_kernel<<<dim3(TT/64, HH, BB), 512, ATTN_SMEM_BYTES>>>();
    // 3) output projection
    gemm_kernel<<<dim3(8, 32), 256, GEMM_SMEM>>>(out, 1, 0);
}

// round 15
// speedup vs baseline: 1.0903x; 1.0903x over previous
#include <cuda_runtime.h>
#include <cuda_fp16.h>
#include <mma.h>
#include <math.h>
#include <cstdint>

using namespace nvcuda;

#define BB 2
#define TT 2048
#define DD 1024
#define HH 16
#define HD 64
#define NROWS (BB*TT)      // 4096
#define WINDOW 128
#define MM (1024*1024)

// ---------------- scratch (device globals: allocation-free) ----------------
__device__ __half g_q[(size_t)BB*HH*TT*HD];   // normalized q (fp16)
__device__ __half g_k[(size_t)BB*HH*TT*HD];   // normalized k (fp16)
__device__ __half g_v[(size_t)BB*HH*TT*HD];   // v (fp16)
__device__ __half g_xh[(size_t)NROWS*DD];     // x (fp16)
__device__ __half g_wh[(size_t)4*MM];         // 32*W (fp16)
__device__ __half g_ath[(size_t)NROWS*DD];    // attention out (fp16)

__device__ __forceinline__ uint32_t smem_u32(const void* p){
    uint32_t a;
    asm("{ .reg .u64 t; cvta.to.shared.u64 t, %1; cvt.u32.u64 %0, t; }" : "=r"(a) : "l"(p));
    return a;
}
__device__ __forceinline__ void cp16(uint32_t s, const void* g){
    asm volatile("cp.async.cg.shared.global [%0], [%1], 16;" :: "r"(s), "l"(g));
}

// =====================================================================
// split prep: x -> fp16 ; W -> fp16(32*W)
// =====================================================================
__global__ void __launch_bounds__(256) split_kernel(
    const float* __restrict__ x,
    const float* __restrict__ wq, const float* __restrict__ wk,
    const float* __restrict__ wv, const float* __restrict__ wo)
{
    size_t fi = (size_t)blockIdx.x*256 + threadIdx.x;
    if (fi < 1048576){
        float4 v = ((const float4*)x)[fi];
        size_t e = fi*4;
        *(half2*)(g_xh+e)   = half2(__float2half(v.x), __float2half(v.y));
        *(half2*)(g_xh+e+2) = half2(__float2half(v.z), __float2half(v.w));
    } else {
        size_t r = fi - 1048576;
        int m = (int)(r >> 18);
        size_t base = r & 262143;
        const float* src = (m==0)?wq:(m==1)?wk:(m==2)?wv:wo;
        float4 v = ((const float4*)src)[base];
        size_t e = (size_t)m*MM + base*4;
        *(half2*)(g_wh+e)   = half2(__float2half(32.0f*v.x), __float2half(32.0f*v.y));
        *(half2*)(g_wh+e+2) = half2(__float2half(32.0f*v.z), __float2half(32.0f*v.w));
    }
}

// =====================================================================
// GEMM (plain fp16, fp32 acc), 2 CTAs/SM. CTA 128x128, warp 64x32, BK=64.
// (R13 configuration — at the legacy-HMMA instruction-rate ceiling)
// =====================================================================
#define NCH 16
#define SSTRIDE 72
#define SARR 9216                        // 128 rows x 72 el
#define STAGE_EL (2*SARR)                // 18432 el
#define STAGE_BY (STAGE_EL*2)            // 36864 B
#define GEMM_SMEM 73728

__global__ void __launch_bounds__(256, 2) gemm_kernel(float* __restrict__ out, int mode)
{
    extern __shared__ __half sb[];
    float* Cs = (float*)sb;                       // [128][132] after mainloop

    const int tid = threadIdx.x, w = tid >> 5, lane = tid & 31;
    const int r0 = blockIdx.y * 128;
    const int nb = blockIdx.x * 128;

    int which, col0;
    const __half* A_h;
    if (mode == 0){ which = nb >> 10; col0 = nb & 1023; A_h = g_xh; }
    else          { which = 3;        col0 = nb;        A_h = g_ath; }
    const __half* W_h = g_wh + (size_t)which*MM;

    const uint32_t ab = smem_u32(sb);

    auto loadc = [&](int c){
        uint32_t st = ab + (uint32_t)(c & 1) * STAGE_BY;
        int ko = c * 64;
        #pragma unroll
        for (int i = 0; i < 4; i++){
            int idx = tid + i*256;
            int row = idx >> 3, seg = idx & 7;
            uint32_t so = (uint32_t)(row*144 + seg*16);
            cp16(st + so,          A_h + (size_t)(r0  + row)*DD + ko + seg*8);
            cp16(st + 18432u + so, W_h + (size_t)(col0 + row)*DD + ko + seg*8);
        }
        asm volatile("cp.async.commit_group;");
    };

    wmma::fragment<wmma::accumulator,16,16,16,float> acc[4][2];
    #pragma unroll
    for (int i = 0; i < 4; i++)
        #pragma unroll
        for (int j = 0; j < 2; j++) wmma::fill_fragment(acc[i][j], 0.0f);

    const int wm = (w >> 2) * 64;
    const int wn = (w & 3) * 32;

    loadc(0);
    for (int c = 0; c < NCH; c++){
        if (c < NCH-1){
            loadc(c+1);
            asm volatile("cp.async.wait_group 1;");
        } else {
            asm volatile("cp.async.wait_group 0;");
        }
        __syncthreads();

        const __half* s = sb + (c & 1) * STAGE_EL;
        const __half* sA = s;
        const __half* sB = s + SARR;

        #pragma unroll
        for (int kk = 0; kk < 64; kk += 16){
            wmma::fragment<wmma::matrix_a,16,16,16,__half,wmma::row_major> af[4];
            wmma::fragment<wmma::matrix_b,16,16,16,__half,wmma::col_major> bf[2];
            #pragma unroll
            for (int i = 0; i < 4; i++)
                wmma::load_matrix_sync(af[i], sA + (wm + i*16)*SSTRIDE + kk, SSTRIDE);
            #pragma unroll
            for (int j = 0; j < 2; j++)
                wmma::load_matrix_sync(bf[j], sB + (wn + j*16)*SSTRIDE + kk, SSTRIDE);
            #pragma unroll
            for (int i = 0; i < 4; i++)
                #pragma unroll
                for (int j = 0; j < 2; j++)
                    wmma::mma_sync(acc[i][j], af[i], bf[j], acc[i][j]);
        }
        __syncthreads();
    }

    #pragma unroll
    for (int i = 0; i < 4; i++)
        #pragma unroll
        for (int j = 0; j < 2; j++)
            wmma::store_matrix_sync(Cs + (wm + i*16)*132 + wn + j*16,
                                    acc[i][j], 132, wmma::mem_row_major);
    __syncthreads();

    const float unsc = 0.03125f;   // 1/32
    #pragma unroll
    for (int rr = 0; rr < 16; rr++){
        int row = w*16 + rr;
        int gt = r0 + row;
        float v0 = Cs[row*132 + lane];
        float v1 = Cs[row*132 + lane + 32];
        float v2 = Cs[row*132 + lane + 64];
        float v3 = Cs[row*132 + lane + 96];
        if (mode == 0){
            float s0 = unsc, s1 = unsc;
            if (which < 2){
                float ssa = v0*v0 + v1*v1;
                float ssb = v2*v2 + v3*v3;
                #pragma unroll
                for (int o = 16; o; o >>= 1){
                    ssa += __shfl_xor_sync(0xffffffffu, ssa, o);
                    ssb += __shfl_xor_sync(0xffffffffu, ssb, o);
                }
                s0 = 1.0f / fmaxf(sqrtf(ssa), 1e-6f);
                s1 = 1.0f / fmaxf(sqrtf(ssb), 1e-6f);
            }
            int bq = gt >> 11, t = gt & (TT-1);
            __half* arr = (which==0) ? g_q : ((which==1) ? g_k : g_v);
            int hh0 = col0 >> 6;
            __half* d0 = arr + ((size_t)(bq*HH + hh0  )*TT + t)*HD;
            __half* d1 = arr + ((size_t)(bq*HH + hh0+1)*TT + t)*HD;
            d0[lane]      = __float2half(v0*s0);
            d0[lane + 32] = __float2half(v1*s0);
            d1[lane]      = __float2half(v2*s1);
            d1[lane + 32] = __float2half(v3*s1);
        } else {
            float* d = out + (size_t)gt*DD + nb;
            d[lane]      = v0*unsc;
            d[lane + 32] = v1*unsc;
            d[lane + 64] = v2*unsc;
            d[lane + 96] = v3*unsc;
        }
    }
}

// =====================================================================
// Attention (fp16 wmma), 512 threads, 2 BLOCKS/SM (90KB smem).
// Softmax v2: live-column iteration (cols = row + lane + 32i, i<4),
// per-lane constant ALiBi bias, NO max-shift (S in [-1,1] -> exp <= e).
// Dead P slots at PV band edges zeroed explicitly.
// smem: Qs[64][72]h Ks[192][72]h Vs[192][72]h Sh[64][200]h = 90112 B
// =====================================================================
#define ATTN_SMEM_BYTES 90112

__global__ void __launch_bounds__(512, 2) attn_kernel()
{
    extern __shared__ __half sm[];
    __half* Qs = sm;                          // [64][72]
    __half* Ks = sm + 4608;                   // [192][72] (dead after QK)
    __half* Vs = sm + 18432;                  // [192][72]
    __half* Sh = sm + 32256;                  // [64][200] half: S, then P in place
    float*  Os = (float*)(sm + 4608);         // [64][68] f32, overlays Ks

    const int tid = threadIdx.x, w = tid >> 5, lane = tid & 31;
    const int q0 = blockIdx.x * 64;
    const int h  = blockIdx.y, b = blockIdx.z;
    const size_t base = ((size_t)(b*HH + h)*TT)*HD;
    const __half* qb = g_q + base;
    const __half* kb = g_k + base;
    const __half* vb = g_v + base;

    {   // Q
        int row = tid >> 3, seg = tid & 7;
        uint4 v = *(const uint4*)(qb + (size_t)(q0 + row)*HD + seg*8);
        *(uint4*)(Qs + row*72 + seg*8) = v;
    }
    #pragma unroll
    for (int it = 0; it < 3; it++){           // K,V
        int idx = tid + it*512;
        int row = idx >> 3, seg = idx & 7;
        int jg = q0 + row;
        uint4 kv = make_uint4(0,0,0,0), vv = make_uint4(0,0,0,0);
        if (jg < TT){
            kv = *(const uint4*)(kb + (size_t)jg*HD + seg*8);
            vv = *(const uint4*)(vb + (size_t)jg*HD + seg*8);
        }
        *(uint4*)(Ks + row*72 + seg*8) = kv;
        *(uint4*)(Vs + row*72 + seg*8) = vv;
    }
    __syncthreads();

    const int wr = w & 3;
    const int wg = w >> 2;

    {   // S = Q @ K^T, fp16 accumulators, live tiles tc = wg*3+f
        wmma::fragment<wmma::accumulator,16,16,16,__half> acc[3];
        #pragma unroll
        for (int f = 0; f < 3; f++) wmma::fill_fragment(acc[f], __float2half(0.0f));
        #pragma unroll
        for (int d = 0; d < HD; d += 16){
            wmma::fragment<wmma::matrix_a,16,16,16,__half,wmma::row_major> af;
            wmma::load_matrix_sync(af, Qs + wr*16*72 + d, 72);
            #pragma unroll
            for (int f = 0; f < 3; f++){
                int tc = wg*3 + f;
                if (tc >= wr && tc <= wr + 8){
                    wmma::fragment<wmma::matrix_b,16,16,16,__half,wmma::col_major> bf;
                    wmma::load_matrix_sync(bf, Ks + tc*16*72 + d, 72);
                    wmma::mma_sync(acc[f], af, bf, acc[f]);
                }
            }
        }
        #pragma unroll
        for (int f = 0; f < 3; f++){
            int tc = wg*3 + f;
            if (tc >= wr && tc <= wr + 8)
                wmma::store_matrix_sync(Sh + wr*16*200 + tc*16, acc[f], 200,
                                        wmma::mem_row_major);
        }
    }
    __syncthreads();

    // softmax v2: warp w -> rows w*4..w*4+3; live cols only; no max-shift.
    const float slope = exp2f(-8.0f * (float)h / 15.0f);
    float bias[4];
    #pragma unroll
    for (int i = 0; i < 4; i++) bias[i] = -(float)(lane + 32*i)*slope;

    #pragma unroll
    for (int rr = 0; rr < 4; rr++){
        int row = w*4 + rr;
        float p[4];
        float sum = 0.0f;
        #pragma unroll
        for (int i = 0; i < 4; i++){
            int col = row + lane + 32*i;             // in [row, row+128)
            bool ok = (q0 + col < TT);
            float pv = ok ? __expf(__half2float(Sh[row*200 + col]) + bias[i]) : 0.0f;
            p[i] = pv; sum += pv;
        }
        #pragma unroll
        for (int o = 16; o; o >>= 1) sum += __shfl_xor_sync(0xffffffffu, sum, o);
        float inv = 1.0f / sum;
        #pragma unroll
        for (int i = 0; i < 4; i++){
            int col = row + lane + 32*i;
            Sh[row*200 + col] = __float2half(p[i]*inv);
        }
        // zero dead P slots inside this row's PV band [16*(row/16), +144)
        int lead = row & 15;                          // dead cols before row
        if (lane < lead)      Sh[row*200 + (row & ~15) + lane] = __float2half(0.0f);
        if (lane < 16 - lead) Sh[row*200 + row + 128 + lane]   = __float2half(0.0f);
    }
    __syncthreads();

    {   // O = P @ V : warp (wr, wg) -> rows wr*16, cols wg*16; 9 live tiles
        wmma::fragment<wmma::accumulator,16,16,16,float> acc;
        wmma::fill_fragment(acc, 0.0f);
        #pragma unroll
        for (int tj = 0; tj < 12; tj++){
            if (tj >= wr && tj <= wr + 8){
                wmma::fragment<wmma::matrix_a,16,16,16,__half,wmma::row_major> af;
                wmma::fragment<wmma::matrix_b,16,16,16,__half,wmma::row_major> bf;
                wmma::load_matrix_sync(af, Sh + wr*16*200 + tj*16, 200);
                wmma::load_matrix_sync(bf, Vs + tj*16*72 + wg*16, 72);
                wmma::mma_sync(acc, af, bf, acc);
            }
        }
        wmma::store_matrix_sync(Os + wr*16*68 + wg*16, acc, 68, wmma::mem_row_major);
    }
    __syncthreads();

    #pragma unroll
    for (int it = 0; it < 2; it++){
        int idx = tid + it*512;
        int row = idx >> 4, c4 = (idx & 15) << 2;
        float4 v = *(const float4*)(Os + row*68 + c4);
        size_t o = (size_t)(b*TT + q0 + row)*DD + h*HD + c4;
        *(half2*)(g_ath+o)   = half2(__float2half(v.x), __float2half(v.y));
        *(half2*)(g_ath+o+2) = half2(__float2half(v.z), __float2half(v.w));
    }
}

// =====================================================================
extern "C" void kernel_launch(void* const* d_in, const int* in_sizes, int n_in,
                              void* d_out, int out_size)
{
    const float* x  = (const float*)d_in[0];
    const float* Wq = (const float*)d_in[1];
    const float* Wk = (const float*)d_in[2];
    const float* Wv = (const float*)d_in[3];
    const float* Wo = (const float*)d_in[4];
    float* out = (float*)d_out;

    cudaFuncSetAttribute(gemm_kernel, cudaFuncAttributeMaxDynamicSharedMemorySize,
                         GEMM_SMEM);
    cudaFuncSetAttribute(attn_kernel, cudaFuncAttributeMaxDynamicSharedMemorySize,
                         ATTN_SMEM_BYTES);

    // 0) fp16 conversion of x and weights (x32)
    split_kernel<<<8192, 256>>>(x, Wq, Wk, Wv, Wo);
    // 1) fused QKV projection + per-head l2norm  [M=4096 x N=3072]
    gemm_kernel<<<dim3(24, 32), 256, GEMM_SMEM>>>(nullptr, 0);
    // 2) sliding-window attention per (b, h, 64-query tile)
    attn_kernel<<<dim3(TT/64, HH, BB), 512, ATTN_SMEM_BYTES>>>();
    // 3) output projection
    gemm_kernel<<<dim3(8, 32), 256, GEMM_SMEM>>>(out, 1);
}

// round 16
// speedup vs baseline: 1.1041x; 1.0126x over previous
#include <cuda_runtime.h>
#include <cuda_fp16.h>
#include <mma.h>
#include <math.h>
#include <cstdint>

using namespace nvcuda;

#define BB 2
#define TT 2048
#define DD 1024
#define HH 16
#define HD 64
#define NROWS (BB*TT)      // 4096
#define WINDOW 128
#define MM (1024*1024)

// ---------------- scratch (device globals: allocation-free) ----------------
__device__ __half g_q[(size_t)BB*HH*TT*HD];   // normalized q (fp16)
__device__ __half g_k[(size_t)BB*HH*TT*HD];   // normalized k (fp16)
__device__ __half g_v[(size_t)BB*HH*TT*HD];   // v (fp16)
__device__ __half g_xh[(size_t)NROWS*DD];     // x (fp16)
__device__ __half g_wh[(size_t)4*MM];         // 32*W (fp16)
__device__ __half g_ath[(size_t)NROWS*DD];    // attention out (fp16)

__device__ __forceinline__ uint32_t smem_u32(const void* p){
    uint32_t a;
    asm("{ .reg .u64 t; cvta.to.shared.u64 t, %1; cvt.u32.u64 %0, t; }" : "=r"(a) : "l"(p));
    return a;
}
__device__ __forceinline__ void cp16(uint32_t s, const void* g){
    asm volatile("cp.async.cg.shared.global [%0], [%1], 16;" :: "r"(s), "l"(g));
}

// =====================================================================
// split prep: x -> fp16 ; W -> fp16(32*W)
// =====================================================================
__global__ void __launch_bounds__(256) split_kernel(
    const float* __restrict__ x,
    const float* __restrict__ wq, const float* __restrict__ wk,
    const float* __restrict__ wv, const float* __restrict__ wo)
{
    size_t fi = (size_t)blockIdx.x*256 + threadIdx.x;
    if (fi < 1048576){
        float4 v = ((const float4*)x)[fi];
        size_t e = fi*4;
        *(half2*)(g_xh+e)   = half2(__float2half(v.x), __float2half(v.y));
        *(half2*)(g_xh+e+2) = half2(__float2half(v.z), __float2half(v.w));
    } else {
        size_t r = fi - 1048576;
        int m = (int)(r >> 18);
        size_t base = r & 262143;
        const float* src = (m==0)?wq:(m==1)?wk:(m==2)?wv:wo;
        float4 v = ((const float4*)src)[base];
        size_t e = (size_t)m*MM + base*4;
        *(half2*)(g_wh+e)   = half2(__float2half(32.0f*v.x), __float2half(32.0f*v.y));
        *(half2*)(g_wh+e+2) = half2(__float2half(32.0f*v.z), __float2half(32.0f*v.w));
    }
}

// =====================================================================
// GEMM (plain fp16, fp32 acc), 2 CTAs/SM. CTA 128x128, warp 64x32, BK=64.
// (frozen — at the legacy-HMMA instruction-rate ceiling)
// =====================================================================
#define NCH 16
#define SSTRIDE 72
#define SARR 9216                        // 128 rows x 72 el
#define STAGE_EL (2*SARR)                // 18432 el
#define STAGE_BY (STAGE_EL*2)            // 36864 B
#define GEMM_SMEM 73728

__global__ void __launch_bounds__(256, 2) gemm_kernel(float* __restrict__ out, int mode)
{
    extern __shared__ __half sb[];
    float* Cs = (float*)sb;                       // [128][132] after mainloop

    const int tid = threadIdx.x, w = tid >> 5, lane = tid & 31;
    const int r0 = blockIdx.y * 128;
    const int nb = blockIdx.x * 128;

    int which, col0;
    const __half* A_h;
    if (mode == 0){ which = nb >> 10; col0 = nb & 1023; A_h = g_xh; }
    else          { which = 3;        col0 = nb;        A_h = g_ath; }
    const __half* W_h = g_wh + (size_t)which*MM;

    const uint32_t ab = smem_u32(sb);

    auto loadc = [&](int c){
        uint32_t st = ab + (uint32_t)(c & 1) * STAGE_BY;
        int ko = c * 64;
        #pragma unroll
        for (int i = 0; i < 4; i++){
            int idx = tid + i*256;
            int row = idx >> 3, seg = idx & 7;
            uint32_t so = (uint32_t)(row*144 + seg*16);
            cp16(st + so,          A_h + (size_t)(r0  + row)*DD + ko + seg*8);
            cp16(st + 18432u + so, W_h + (size_t)(col0 + row)*DD + ko + seg*8);
        }
        asm volatile("cp.async.commit_group;");
    };

    wmma::fragment<wmma::accumulator,16,16,16,float> acc[4][2];
    #pragma unroll
    for (int i = 0; i < 4; i++)
        #pragma unroll
        for (int j = 0; j < 2; j++) wmma::fill_fragment(acc[i][j], 0.0f);

    const int wm = (w >> 2) * 64;
    const int wn = (w & 3) * 32;

    loadc(0);
    for (int c = 0; c < NCH; c++){
        if (c < NCH-1){
            loadc(c+1);
            asm volatile("cp.async.wait_group 1;");
        } else {
            asm volatile("cp.async.wait_group 0;");
        }
        __syncthreads();

        const __half* s = sb + (c & 1) * STAGE_EL;
        const __half* sA = s;
        const __half* sB = s + SARR;

        #pragma unroll
        for (int kk = 0; kk < 64; kk += 16){
            wmma::fragment<wmma::matrix_a,16,16,16,__half,wmma::row_major> af[4];
            wmma::fragment<wmma::matrix_b,16,16,16,__half,wmma::col_major> bf[2];
            #pragma unroll
            for (int i = 0; i < 4; i++)
                wmma::load_matrix_sync(af[i], sA + (wm + i*16)*SSTRIDE + kk, SSTRIDE);
            #pragma unroll
            for (int j = 0; j < 2; j++)
                wmma::load_matrix_sync(bf[j], sB + (wn + j*16)*SSTRIDE + kk, SSTRIDE);
            #pragma unroll
            for (int i = 0; i < 4; i++)
                #pragma unroll
                for (int j = 0; j < 2; j++)
                    wmma::mma_sync(acc[i][j], af[i], bf[j], acc[i][j]);
        }
        __syncthreads();
    }

    #pragma unroll
    for (int i = 0; i < 4; i++)
        #pragma unroll
        for (int j = 0; j < 2; j++)
            wmma::store_matrix_sync(Cs + (wm + i*16)*132 + wn + j*16,
                                    acc[i][j], 132, wmma::mem_row_major);
    __syncthreads();

    const float unsc = 0.03125f;   // 1/32
    #pragma unroll
    for (int rr = 0; rr < 16; rr++){
        int row = w*16 + rr;
        int gt = r0 + row;
        float v0 = Cs[row*132 + lane];
        float v1 = Cs[row*132 + lane + 32];
        float v2 = Cs[row*132 + lane + 64];
        float v3 = Cs[row*132 + lane + 96];
        if (mode == 0){
            float s0 = unsc, s1 = unsc;
            if (which < 2){
                float ssa = v0*v0 + v1*v1;
                float ssb = v2*v2 + v3*v3;
                #pragma unroll
                for (int o = 16; o; o >>= 1){
                    ssa += __shfl_xor_sync(0xffffffffu, ssa, o);
                    ssb += __shfl_xor_sync(0xffffffffu, ssb, o);
                }
                s0 = 1.0f / fmaxf(sqrtf(ssa), 1e-6f);
                s1 = 1.0f / fmaxf(sqrtf(ssb), 1e-6f);
            }
            int bq = gt >> 11, t = gt & (TT-1);
            __half* arr = (which==0) ? g_q : ((which==1) ? g_k : g_v);
            int hh0 = col0 >> 6;
            __half* d0 = arr + ((size_t)(bq*HH + hh0  )*TT + t)*HD;
            __half* d1 = arr + ((size_t)(bq*HH + hh0+1)*TT + t)*HD;
            d0[lane]      = __float2half(v0*s0);
            d0[lane + 32] = __float2half(v1*s0);
            d1[lane]      = __float2half(v2*s1);
            d1[lane + 32] = __float2half(v3*s1);
        } else {
            float* d = out + (size_t)gt*DD + nb;
            d[lane]      = v0*unsc;
            d[lane + 32] = v1*unsc;
            d[lane + 64] = v2*unsc;
            d[lane + 96] = v3*unsc;
        }
    }
}

// =====================================================================
// Attention (fp16 wmma), 512 threads, 2 BLOCKS/SM (90KB smem).
// Loads via cp.async (fast path for full tiles; boundary tile zero-fills).
// Softmax: live cols only, per-lane ALiBi, no max-shift. P in place.
// smem: Qs[64][72]h Ks[192][72]h Vs[192][72]h Sh[64][200]h = 90112 B
// =====================================================================
#define ATTN_SMEM_BYTES 90112

__global__ void __launch_bounds__(512, 2) attn_kernel()
{
    extern __shared__ __half sm[];
    __half* Qs = sm;                          // [64][72]      bytes [0, 9216)
    __half* Ks = sm + 4608;                   // [192][72]     bytes [9216, 36864)
    __half* Vs = sm + 18432;                  // [192][72]     bytes [36864, 64512)
    __half* Sh = sm + 32256;                  // [64][200]     bytes [64512, 90112)
    float*  Os = (float*)(sm + 4608);         // [64][68] f32 overlays Ks

    const int tid = threadIdx.x, w = tid >> 5, lane = tid & 31;
    const int q0 = blockIdx.x * 64;
    const int h  = blockIdx.y, b = blockIdx.z;
    const size_t base = ((size_t)(b*HH + h)*TT)*HD;
    const __half* qb = g_q + base;
    const __half* kb = g_k + base;
    const __half* vb = g_v + base;

    const uint32_t ab = smem_u32(sm);

    {   // Q: 64 rows x 8 segs = 512 cp.asyncs (always full)
        int row = tid >> 3, seg = tid & 7;
        cp16(ab + (uint32_t)(row*144 + seg*16), qb + (size_t)(q0 + row)*HD + seg*8);
    }
    if (q0 + 192 <= TT){
        // fast path: full 192-row K/V tile
        #pragma unroll
        for (int it = 0; it < 3; it++){
            int idx = tid + it*512;
            int row = idx >> 3, seg = idx & 7;
            uint32_t so = (uint32_t)(row*144 + seg*16);
            size_t go = (size_t)(q0 + row)*HD + seg*8;
            cp16(ab + 9216u  + so, kb + go);
            cp16(ab + 36864u + so, vb + go);
        }
    } else {
        // boundary tile: valid rows via cp.async, others zero via STS
        #pragma unroll
        for (int it = 0; it < 3; it++){
            int idx = tid + it*512;
            int row = idx >> 3, seg = idx & 7;
            uint32_t so = (uint32_t)(row*144 + seg*16);
            if (q0 + row < TT){
                size_t go = (size_t)(q0 + row)*HD + seg*8;
                cp16(ab + 9216u  + so, kb + go);
                cp16(ab + 36864u + so, vb + go);
            } else {
                uint4 z = make_uint4(0,0,0,0);
                *(uint4*)(Ks + row*72 + seg*8) = z;
                *(uint4*)(Vs + row*72 + seg*8) = z;
            }
        }
    }
    asm volatile("cp.async.commit_group;");
    asm volatile("cp.async.wait_group 0;");
    __syncthreads();

    const int wr = w & 3;
    const int wg = w >> 2;

    {   // S = Q @ K^T, fp16 accumulators, live tiles tc = wg*3+f
        wmma::fragment<wmma::accumulator,16,16,16,__half> acc[3];
        #pragma unroll
        for (int f = 0; f < 3; f++) wmma::fill_fragment(acc[f], __float2half(0.0f));
        #pragma unroll
        for (int d = 0; d < HD; d += 16){
            wmma::fragment<wmma::matrix_a,16,16,16,__half,wmma::row_major> af;
            wmma::load_matrix_sync(af, Qs + wr*16*72 + d, 72);
            #pragma unroll
            for (int f = 0; f < 3; f++){
                int tc = wg*3 + f;
                if (tc >= wr && tc <= wr + 8){
                    wmma::fragment<wmma::matrix_b,16,16,16,__half,wmma::col_major> bf;
                    wmma::load_matrix_sync(bf, Ks + tc*16*72 + d, 72);
                    wmma::mma_sync(acc[f], af, bf, acc[f]);
                }
            }
        }
        #pragma unroll
        for (int f = 0; f < 3; f++){
            int tc = wg*3 + f;
            if (tc >= wr && tc <= wr + 8)
                wmma::store_matrix_sync(Sh + wr*16*200 + tc*16, acc[f], 200,
                                        wmma::mem_row_major);
        }
    }
    __syncthreads();

    // softmax: warp w -> rows w*4..w*4+3; live cols only; no max-shift.
    const float slope = exp2f(-8.0f * (float)h / 15.0f);
    float bias[4];
    #pragma unroll
    for (int i = 0; i < 4; i++) bias[i] = -(float)(lane + 32*i)*slope;

    #pragma unroll
    for (int rr = 0; rr < 4; rr++){
        int row = w*4 + rr;
        float p[4];
        float sum = 0.0f;
        #pragma unroll
        for (int i = 0; i < 4; i++){
            int col = row + lane + 32*i;             // in [row, row+128)
            bool ok = (q0 + col < TT);
            float pv = ok ? __expf(__half2float(Sh[row*200 + col]) + bias[i]) : 0.0f;
            p[i] = pv; sum += pv;
        }
        #pragma unroll
        for (int o = 16; o; o >>= 1) sum += __shfl_xor_sync(0xffffffffu, sum, o);
        float inv = 1.0f / sum;
        #pragma unroll
        for (int i = 0; i < 4; i++){
            int col = row + lane + 32*i;
            Sh[row*200 + col] = __float2half(p[i]*inv);
        }
        int lead = row & 15;
        if (lane < lead)      Sh[row*200 + (row & ~15) + lane] = __float2half(0.0f);
        if (lane < 16 - lead) Sh[row*200 + row + 128 + lane]   = __float2half(0.0f);
    }
    __syncthreads();

    {   // O = P @ V : warp (wr, wg) -> rows wr*16, cols wg*16; 9 live tiles
        wmma::fragment<wmma::accumulator,16,16,16,float> acc;
        wmma::fill_fragment(acc, 0.0f);
        #pragma unroll
        for (int tj = 0; tj < 12; tj++){
            if (tj >= wr && tj <= wr + 8){
                wmma::fragment<wmma::matrix_a,16,16,16,__half,wmma::row_major> af;
                wmma::fragment<wmma::matrix_b,16,16,16,__half,wmma::row_major> bf;
                wmma::load_matrix_sync(af, Sh + wr*16*200 + tj*16, 200);
                wmma::load_matrix_sync(bf, Vs + tj*16*72 + wg*16, 72);
                wmma::mma_sync(acc, af, bf, acc);
            }
        }
        wmma::store_matrix_sync(Os + wr*16*68 + wg*16, acc, 68, wmma::mem_row_major);
    }
    __syncthreads();

    #pragma unroll
    for (int it = 0; it < 2; it++){
        int idx = tid + it*512;
        int row = idx >> 4, c4 = (idx & 15) << 2;
        float4 v = *(const float4*)(Os + row*68 + c4);
        size_t o = (size_t)(b*TT + q0 + row)*DD + h*HD + c4;
        *(half2*)(g_ath+o)   = half2(__float2half(v.x), __float2half(v.y));
        *(half2*)(g_ath+o+2) = half2(__float2half(v.z), __float2half(v.w));
    }
}

// =====================================================================
extern "C" void kernel_launch(void* const* d_in, const int* in_sizes, int n_in,
                              void* d_out, int out_size)
{
    const float* x  = (const float*)d_in[0];
    const float* Wq = (const float*)d_in[1];
    const float* Wk = (const float*)d_in[2];
    const float* Wv = (const float*)d_in[3];
    const float* Wo = (const float*)d_in[4];
    float* out = (float*)d_out;

    cudaFuncSetAttribute(gemm_kernel, cudaFuncAttributeMaxDynamicSharedMemorySize,
                         GEMM_SMEM);
    cudaFuncSetAttribute(attn_kernel, cudaFuncAttributeMaxDynamicSharedMemorySize,
                         ATTN_SMEM_BYTES);

    // 0) fp16 conversion of x and weights (x32)
    split_kernel<<<8192, 256>>>(x, Wq, Wk, Wv, Wo);
    // 1) fused QKV projection + per-head l2norm  [M=4096 x N=3072]
    gemm_kernel<<<dim3(24, 32), 256, GEMM_SMEM>>>(nullptr, 0);
    // 2) sliding-window attention per (b, h, 64-query tile)
    attn_kernel<<<dim3(TT/64, HH, BB), 512, ATTN_SMEM_BYTES>>>();
    // 3) output projection
    gemm_kernel<<<dim3(8, 32), 256, GEMM_SMEM>>>(out, 1);
}